// round 16
// baseline (speedup 1.0000x reference)
#include <cuda_runtime.h>

#define BB 16
#define HH 2048
#define WW 2048
#define SS 5000
#define TOTAL (BB * SS)            // 80000 stations
#define THREADS 160                // 5 warps; each thread does 2 stations
#define SPT 2
#define NBLK (TOTAL / (THREADS * SPT))   // 250 blocks
#define NWARP (THREADS / 32)             // 5

__device__ float        g_partials[NBLK];
__device__ unsigned int g_count;   // zero at module load; re-armed by last block

__device__ __forceinline__ unsigned atomic_inc_acqrel(unsigned int* p) {
    unsigned old;
    asm volatile("atom.acq_rel.gpu.global.add.u32 %0, [%1], %2;"
                 : "=r"(old) : "l"(p), "r"(1u) : "memory");
    return old;
}

__device__ __forceinline__ float warp_reduce(float v) {
    #pragma unroll
    for (int off = 16; off > 0; off >>= 1)
        v += __shfl_down_sync(0xFFFFFFFFu, v, off);
    return v;
}

// Compute one station's squared error given its already-loaded position.
// Fast path issues its float4 loads; caller arranges two stations' loads to
// be independent so they overlap in the memory pipeline.
__device__ __forceinline__ float station_err2(const float* __restrict__ pred,
                                              const float* __restrict__ runoff,
                                              int idx, int px, int py)
{
    int b = idx / SS;
    const float* base = pred + (size_t)b * (size_t)(HH * WW);
    float avg;

    if (px >= 1 && px <= WW - 2 && py >= 1 && py <= HH - 2) {
        int a4  = (px - 1) >> 2;
        int off = (px - 1) & 3;
        const float4* r0 = reinterpret_cast<const float4*>(base + (size_t)(py - 1) * WW) + a4;
        const float4* r1 = reinterpret_cast<const float4*>(base + (size_t)(py    ) * WW) + a4;
        const float4* r2 = reinterpret_cast<const float4*>(base + (size_t)(py + 1) * WW) + a4;

        // Front-batch all loads (up to 6) before any arithmetic.
        float4 v00 = __ldg(r0), v10 = __ldg(r1), v20 = __ldg(r2);
        float4 v01 = make_float4(0.f,0.f,0.f,0.f);
        float4 v11 = v01, v21 = v01;
        if (off >= 2) { v01 = __ldg(r0 + 1); v11 = __ldg(r1 + 1); v21 = __ldg(r2 + 1); }

        float s0, s1, s2;
        if      (off == 0) { s0 = v00.x+v00.y+v00.z; s1 = v10.x+v10.y+v10.z; s2 = v20.x+v20.y+v20.z; }
        else if (off == 1) { s0 = v00.y+v00.z+v00.w; s1 = v10.y+v10.z+v10.w; s2 = v20.y+v20.z+v20.w; }
        else if (off == 2) { s0 = v00.z+v00.w+v01.x; s1 = v10.z+v10.w+v11.x; s2 = v20.z+v20.w+v21.x; }
        else               { s0 = v00.w+v01.x+v01.y; s1 = v10.w+v11.x+v11.y; s2 = v20.w+v21.x+v21.y; }
        avg = (s0 + s1 + s2) * (1.0f / 9.0f);
    } else {
        float sum = 0.0f, cnt = 0.0f;
        #pragma unroll
        for (int dy = -1; dy <= 1; ++dy) {
            int y   = py + dy;
            bool vy = (y >= 0) & (y < HH);
            int yc  = min(max(y, 0), HH - 1);
            const float* row = base + (size_t)yc * WW;
            #pragma unroll
            for (int dx = -1; dx <= 1; ++dx) {
                int x  = px + dx;
                bool v = vy & (x >= 0) & (x < WW);
                int xc = min(max(x, 0), WW - 1);
                float val = __ldg(row + xc);
                sum += v ? val  : 0.0f;
                cnt += v ? 1.0f : 0.0f;
            }
        }
        avg = sum / cnt;
    }

    float d = avg - __ldg(runoff + idx);
    return d * d;
}

__global__ void __launch_bounds__(THREADS)
station_loss_kernel(const float* __restrict__ pred,
                    const int*   __restrict__ pos,
                    const float* __restrict__ runoff,
                    float*       __restrict__ out)
{
    int base = blockIdx.x * (THREADS * SPT);
    int i0   = base + threadIdx.x;            // station 0 (coalesced)
    int i1   = i0 + THREADS;                  // station 1 (coalesced)

    // Front-load both positions — independent, overlap in flight.
    int2 p0 = __ldg(reinterpret_cast<const int2*>(pos) + i0);
    int2 p1 = __ldg(reinterpret_cast<const int2*>(pos) + i1);

    // Two stations' gathers are independent; ptxas batches their LDGs,
    // roughly doubling per-thread MLP vs one-station-per-thread.
    float err2 = station_err2(pred, runoff, i0, p0.x, p0.y)
               + station_err2(pred, runoff, i1, p1.x, p1.y);

    // Deterministic block reduction: warp shuffle then fixed-order sum of 5.
    __shared__ float warp_sums[NWARP];
    err2 = warp_reduce(err2);

    int lane = threadIdx.x & 31;
    int wid  = threadIdx.x >> 5;
    if (lane == 0) warp_sums[wid] = err2;
    __syncthreads();

    __shared__ bool is_last;
    if (threadIdx.x == 0) {
        float v = 0.0f;
        #pragma unroll
        for (int i = 0; i < NWARP; ++i)
            v += warp_sums[i];
        g_partials[blockIdx.x] = v;
        unsigned done = atomic_inc_acqrel(&g_count);   // release orders the store
        is_last = (done == NBLK - 1);
    }
    __syncthreads();

    // Last block: deterministic final reduction over 250 partials.
    if (is_last) {
        float v = 0.0f;
        for (int i = threadIdx.x; i < NBLK; i += THREADS)
            v += __ldcg(&g_partials[i]);
        v = warp_reduce(v);

        __shared__ float fin[NWARP];
        if (lane == 0) fin[wid] = v;
        __syncthreads();
        if (threadIdx.x == 0) {
            float s = 0.0f;
            #pragma unroll
            for (int i = 0; i < NWARP; ++i)
                s += fin[i];
            out[0]  = s / (float)TOTAL;
            g_count = 0u;   // re-arm for next graph replay
        }
    }
}

extern "C" void kernel_launch(void* const* d_in, const int* in_sizes, int n_in,
                              void* d_out, int out_size)
{
    const float* pred   = (const float*)d_in[0];  // (B,1,H,W) f32
    const int*   pos    = (const int*)  d_in[1];  // (B,S,2)  i32
    const float* runoff = (const float*)d_in[2];  // (B,S)    f32
    float* out = (float*)d_out;

    station_loss_kernel<<<NBLK, THREADS>>>(pred, pos, runoff, out);
}